// round 12
// baseline (speedup 1.0000x reference)
#include <cuda_runtime.h>
#include <cuda_bf16.h>
#include <cstdint>

// out[n][s] = dot(x[n,:], weight[ids[s],:]) + bias[ids[s]]
//   x [256,512] f32, weight [500001,512] f32, bias [500001] f32, ids [32768] i32
//   out [256, 32768] f32
// Round 12: TF32 mma.sync, CTA 128x128, 4 warps (64x64 warp tile), KC=32.
// - A fed as RAW f32 (HW truncates to tf32); B pre-rounded RNA. No in-loop cvt.
// - 2-stage cp.async pipeline (64KB) + 64x132 epilogue buffer -> 3 CTAs/SM.

namespace {
constexpr int D_K    = 512;
constexpr int NX     = 256;
constexpr int S_ALL  = 32768;
constexpr int ROWS_W = 500001;
constexpr int STILE  = 128;        // samples per CTA (GEMM M)
constexpr int NTILE  = 128;        // x rows per CTA (GEMM N)
constexpr int KC     = 32;         // f32 K elems per chunk
constexpr int NCH    = D_K / KC;   // 16
constexpr int THREADS = 128;
constexpr int NSTAGE = 2;

// stage layout (bytes): A 128 rows x 128B, B 128 rows x 128B
constexpr uint32_t A_OFF = 0;          // 16KB
constexpr uint32_t B_OFF = 16384;      // 16KB
constexpr uint32_t STAGE = 32768;      // 32KB
constexpr uint32_t SMEM_BYTES = NSTAGE * STAGE;  // 64KB; epilogue C (33.8KB) reuses
constexpr int CSTRIDE = 132;           // C is [n][m], 64 rows per pass
}

__device__ float g_xt[NX * D_K];       // x pre-rounded to tf32 (RNA)

__device__ __forceinline__ uint32_t smem_u32(const void* p) {
    uint32_t a;
    asm("{ .reg .u64 t; cvta.to.shared.u64 t, %1; cvt.u32.u64 %0, t; }" : "=r"(a) : "l"(p));
    return a;
}
__device__ __forceinline__ uint32_t sw128(uint32_t o) { return o ^ ((o >> 3) & 0x70u); }

__device__ __forceinline__ uint32_t cvt_tf32(float v) {
    uint32_t r;
    asm("cvt.rna.tf32.f32 %0, %1;" : "=r"(r) : "f"(v));
    return r;
}
__device__ __forceinline__ void ldsm4(uint32_t addr, uint32_t& r0, uint32_t& r1,
                                      uint32_t& r2, uint32_t& r3) {
    asm volatile("ldmatrix.sync.aligned.m8n8.x4.shared.b16 {%0,%1,%2,%3}, [%4];"
                 : "=r"(r0), "=r"(r1), "=r"(r2), "=r"(r3) : "r"(addr));
}
__device__ __forceinline__ void mma_tf32(float* d, const uint32_t* a, const uint32_t* b) {
    asm volatile(
        "mma.sync.aligned.m16n8k8.row.col.f32.tf32.tf32.f32 "
        "{%0,%1,%2,%3}, {%4,%5,%6,%7}, {%8,%9}, {%0,%1,%2,%3};"
        : "+f"(d[0]), "+f"(d[1]), "+f"(d[2]), "+f"(d[3])
        : "r"(a[0]), "r"(a[1]), "r"(a[2]), "r"(a[3]), "r"(b[0]), "r"(b[1]));
}
__device__ __forceinline__ void cp16(uint32_t dst, const void* src) {
    asm volatile("cp.async.ca.shared.global [%0], [%1], 16;" :: "r"(dst), "l"(src));
}
__device__ __forceinline__ void cp_commit() {
    asm volatile("cp.async.commit_group;" ::: "memory");
}
template <int N>
__device__ __forceinline__ void cp_wait() {
    asm volatile("cp.async.wait_group %0;" :: "n"(N) : "memory");
}

// ---------- kernel 1: round x to tf32 (RNA) ----------
__global__ void round_x_kernel(const float* __restrict__ x) {
    int i = blockIdx.x * blockDim.x + threadIdx.x;   // over 32768 float4s
    float4 v = reinterpret_cast<const float4*>(x)[i];
    uint4 t;
    t.x = cvt_tf32(v.x); t.y = cvt_tf32(v.y);
    t.z = cvt_tf32(v.z); t.w = cvt_tf32(v.w);
    reinterpret_cast<uint4*>(g_xt)[i] = t;
}

// ---------- kernel 2: GEMM ----------
__global__ void __launch_bounds__(THREADS, 3)
lsh_mma_gemm(const float* __restrict__ weight,
             const float* __restrict__ bias,
             const int* __restrict__ sample_ids,
             float* __restrict__ out)
{
    extern __shared__ float4 smem4[];
    char* smc = reinterpret_cast<char*>(smem4);
    const uint32_t sb = smem_u32(smc);

    __shared__ int   sids[STILE];
    __shared__ float sbias[STILE];

    const int tid = threadIdx.x;
    const int wid = tid >> 5;
    const int lid = tid & 31;
    const int n0  = blockIdx.x * NTILE;    // x-row half (0 or 128)
    const int s0  = blockIdx.y * STILE;    // sample tile

    {
        int id = sample_ids[s0 + tid];
        id = min(max(id, 0), ROWS_W - 1);
        sids[tid]  = id;
        sbias[tid] = bias[id];
    }
    __syncthreads();

    // ---- loader coords: each thread fills fixed seg of 8 rows (A and B) ----
    const int l_sg  = tid & 7;               // 16B segment within 128B row
    const int l_rw0 = tid >> 3;              // base row (j adds 16)

    // ---- warp / mma coords: 2(M) x 2(N), warp tile 64x64 ----
    const int warp_m = wid & 1;
    const int warp_n = wid >> 1;
    const uint32_t l_row = (uint32_t)((lid & 7) + ((lid >> 3) & 1) * 8);
    const uint32_t l_k   = (uint32_t)(lid >> 4) * 4u;     // f32 col offset

    const uint32_t a_rb0 = ((uint32_t)(warp_m * 64) + l_row) * 128u;  // mt adds 16*128
    const uint32_t b_rb0 = ((uint32_t)(warp_n * 64) + l_row) * 128u;  // nf2 adds 16*128

    float d[4][8][4];
    #pragma unroll
    for (int mt = 0; mt < 4; mt++)
        #pragma unroll
        for (int nf = 0; nf < 8; nf++)
            #pragma unroll
            for (int r = 0; r < 4; r++) d[mt][nf][r] = 0.f;

    // issue one stage's A (raw f32 gather) + B copies, then commit the group
    auto issue_stage = [&](int c, uint32_t stg) {
        #pragma unroll
        for (int j = 0; j < 8; j++) {
            int row = l_rw0 + j * 16;
            uint32_t o = sw128((uint32_t)row * 128u + (uint32_t)l_sg * 16u);
            const float* asrc = weight + (size_t)sids[row] * D_K + c * KC + l_sg * 4;
            cp16(sb + stg + A_OFF + o, asrc);
            const float* bsrc = g_xt + (size_t)(n0 + row) * D_K + c * KC + l_sg * 4;
            cp16(sb + stg + B_OFF + o, bsrc);
        }
        cp_commit();
    };

    // ---------- prologue: stages 0, 1 ----------
    issue_stage(0, 0);
    issue_stage(1, STAGE);

    // ---------- main loop (2-stage: wait, bar, compute, bar, issue) ----------
    for (int c = 0; c < NCH; c++) {
        cp_wait<1>();                        // chunk c complete (c+1 may be in flight)
        __syncthreads();

        const uint32_t cur = (uint32_t)(c & 1) * STAGE;

        // ---- compute chunk c: 4 k-steps of 8 ----
        #pragma unroll
        for (int ks8 = 0; ks8 < 4; ks8++) {
            const uint32_t kb = ((uint32_t)ks8 * 8u + l_k) * 4u;   // byte col (<128)
            uint32_t a[4][4];
            #pragma unroll
            for (int mt = 0; mt < 4; mt++) {
                uint32_t off = sw128(a_rb0 + (uint32_t)mt * 2048u + kb);
                // raw f32 bits: HMMA.TF32 ignores low mantissa bits (RZ truncation)
                ldsm4(sb + cur + A_OFF + off, a[mt][0], a[mt][1], a[mt][2], a[mt][3]);
            }
            #pragma unroll
            for (int h = 0; h < 2; h++) {          // two nf-halves: caps B frag regs
                uint32_t b[4][2];
                #pragma unroll
                for (int i = 0; i < 2; i++) {
                    int nf2 = h * 2 + i;
                    uint32_t off = sw128(b_rb0 + (uint32_t)nf2 * 2048u + kb);
                    // x4 over 16 n-rows: r0/r2 -> nf even, r1/r3 -> nf odd
                    ldsm4(sb + cur + B_OFF + off, b[2*i][0], b[2*i+1][0],
                          b[2*i][1], b[2*i+1][1]);
                }
                #pragma unroll
                for (int mt = 0; mt < 4; mt++)
                    #pragma unroll
                    for (int j = 0; j < 4; j++)
                        mma_tf32(d[mt][h * 4 + j], a[mt], b[j]);
            }
        }

        __syncthreads();                     // all warps done reading buffer (c&1)

        if (c + 2 < NCH) issue_stage(c + 2, cur);   // refill the buffer just freed
        else             cp_commit();        // keep group count in step for cp_wait<1>
    }

    // ---------- epilogue: two n-passes through 64x132 C buffer ----------
    float* C = reinterpret_cast<float*>(smc);   // 64 x 132 f32 = 33.8KB
    #pragma unroll
    for (int p = 0; p < 2; p++) {
        if (warp_n == p) {
            #pragma unroll
            for (int mt = 0; mt < 4; mt++) {
                int m = warp_m * 64 + mt * 16 + (lid >> 2);
                float b0v = sbias[m];
                float b1v = sbias[m + 8];
                #pragma unroll
                for (int nf = 0; nf < 8; nf++) {
                    int nr = nf * 8 + (lid & 3) * 2;   // 0..63 within this n-half
                    C[(size_t)nr * CSTRIDE + m]           = d[mt][nf][0] + b0v;
                    C[(size_t)(nr + 1) * CSTRIDE + m]     = d[mt][nf][1] + b0v;
                    C[(size_t)nr * CSTRIDE + m + 8]       = d[mt][nf][2] + b1v;
                    C[(size_t)(nr + 1) * CSTRIDE + m + 8] = d[mt][nf][3] + b1v;
                }
            }
        }
        __syncthreads();
        // all warps: 16 rows each, coalesced float4 stores
        #pragma unroll
        for (int j = 0; j < 16; j++) {
            int nr = wid * 16 + j;
            float4 v = *reinterpret_cast<const float4*>(&C[(size_t)nr * CSTRIDE + lid * 4]);
            *reinterpret_cast<float4*>(
                out + (size_t)(n0 + p * 64 + nr) * S_ALL + s0 + lid * 4) = v;
        }
        __syncthreads();
    }
}

extern "C" void kernel_launch(void* const* d_in, const int* in_sizes, int n_in,
                              void* d_out, int out_size)
{
    const float* x    = (const float*)d_in[0];
    const float* w    = (const float*)d_in[1];
    const float* bias = (const float*)d_in[2];
    const int*   ids  = (const int*)d_in[3];
    float*       out  = (float*)d_out;

    cudaFuncSetAttribute(lsh_mma_gemm, cudaFuncAttributeMaxDynamicSharedMemorySize,
                         SMEM_BYTES);

    round_x_kernel<<<128, 256>>>(x);
    dim3 grid(NX / NTILE, S_ALL / STILE);   // (2, 256): n-half fastest -> L2 reuse
    lsh_mma_gemm<<<grid, THREADS, SMEM_BYTES>>>(w, bias, ids, out);
}

// round 16
// speedup vs baseline: 1.4127x; 1.4127x over previous
#include <cuda_runtime.h>
#include <cuda_bf16.h>
#include <cstdint>

// out[n][s] = dot(x[n,:], weight[ids[s],:]) + bias[ids[s]]
//   x [256,512] f32, weight [500001,512] f32, bias [500001] f32, ids [32768] i32
//   out [256, 32768] f32
// Round 13: TF32 mma.sync, CTA 128x128, 8 warps (2Mx4N, warp tile 64x32),
// KC=32. All-cp.async (A raw f32 -> HW tf32 truncation, B RNA-pre-rounded),
// 2-stage pipeline, ~110 live regs -> 2 CTAs x 256 thr = 16 warps/SM.

namespace {
constexpr int D_K    = 512;
constexpr int NX     = 256;
constexpr int S_ALL  = 32768;
constexpr int ROWS_W = 500001;
constexpr int STILE  = 128;        // samples per CTA (GEMM M)
constexpr int NTILE  = 128;        // x rows per CTA (GEMM N)
constexpr int KC     = 32;         // f32 K elems per chunk
constexpr int NCH    = D_K / KC;   // 16
constexpr int THREADS = 256;
constexpr int NSTAGE = 2;

// stage layout (bytes): A 128 rows x 128B, B 128 rows x 128B
constexpr uint32_t A_OFF = 0;          // 16KB
constexpr uint32_t B_OFF = 16384;      // 16KB
constexpr uint32_t STAGE = 32768;      // 32KB
constexpr uint32_t SMEM_BYTES = 69632; // 68KB: 2 stages + epilogue C (67.6KB) reuse
constexpr int CSTRIDE = 132;           // C is [n][m] with stride 132 f32
}

__device__ float g_xt[NX * D_K];       // x pre-rounded to tf32 (RNA)

__device__ __forceinline__ uint32_t smem_u32(const void* p) {
    uint32_t a;
    asm("{ .reg .u64 t; cvta.to.shared.u64 t, %1; cvt.u32.u64 %0, t; }" : "=r"(a) : "l"(p));
    return a;
}
__device__ __forceinline__ uint32_t sw128(uint32_t o) { return o ^ ((o >> 3) & 0x70u); }

__device__ __forceinline__ uint32_t cvt_tf32(float v) {
    uint32_t r;
    asm("cvt.rna.tf32.f32 %0, %1;" : "=r"(r) : "f"(v));
    return r;
}
__device__ __forceinline__ void ldsm4(uint32_t addr, uint32_t& r0, uint32_t& r1,
                                      uint32_t& r2, uint32_t& r3) {
    asm volatile("ldmatrix.sync.aligned.m8n8.x4.shared.b16 {%0,%1,%2,%3}, [%4];"
                 : "=r"(r0), "=r"(r1), "=r"(r2), "=r"(r3) : "r"(addr));
}
__device__ __forceinline__ void mma_tf32(float* d, const uint32_t* a, const uint32_t* b) {
    asm volatile(
        "mma.sync.aligned.m16n8k8.row.col.f32.tf32.tf32.f32 "
        "{%0,%1,%2,%3}, {%4,%5,%6,%7}, {%8,%9}, {%0,%1,%2,%3};"
        : "+f"(d[0]), "+f"(d[1]), "+f"(d[2]), "+f"(d[3])
        : "r"(a[0]), "r"(a[1]), "r"(a[2]), "r"(a[3]), "r"(b[0]), "r"(b[1]));
}
__device__ __forceinline__ void cp16(uint32_t dst, const void* src) {
    asm volatile("cp.async.ca.shared.global [%0], [%1], 16;" :: "r"(dst), "l"(src));
}
__device__ __forceinline__ void cp_commit() {
    asm volatile("cp.async.commit_group;" ::: "memory");
}
template <int N>
__device__ __forceinline__ void cp_wait() {
    asm volatile("cp.async.wait_group %0;" :: "n"(N) : "memory");
}

// ---------- kernel 1: round x to tf32 (RNA) ----------
__global__ void round_x_kernel(const float* __restrict__ x) {
    int i = blockIdx.x * blockDim.x + threadIdx.x;   // over 32768 float4s
    float4 v = reinterpret_cast<const float4*>(x)[i];
    uint4 t;
    t.x = cvt_tf32(v.x); t.y = cvt_tf32(v.y);
    t.z = cvt_tf32(v.z); t.w = cvt_tf32(v.w);
    reinterpret_cast<uint4*>(g_xt)[i] = t;
}

// ---------- kernel 2: GEMM ----------
__global__ void __launch_bounds__(THREADS, 2)
lsh_mma_gemm(const float* __restrict__ weight,
             const float* __restrict__ bias,
             const int* __restrict__ sample_ids,
             float* __restrict__ out)
{
    extern __shared__ float4 smem4[];
    char* smc = reinterpret_cast<char*>(smem4);
    const uint32_t sb = smem_u32(smc);

    __shared__ int   sids[STILE];
    __shared__ float sbias[STILE];

    const int tid = threadIdx.x;
    const int wid = tid >> 5;
    const int lid = tid & 31;
    const int n0  = blockIdx.x * NTILE;    // x-row half (0 or 128)
    const int s0  = blockIdx.y * STILE;    // sample tile

    if (tid < STILE) {
        int id = sample_ids[s0 + tid];
        id = min(max(id, 0), ROWS_W - 1);
        sids[tid]  = id;
        sbias[tid] = bias[id];
    }
    __syncthreads();

    // ---- loader coords: 128 rows x 8 segs, 256 threads -> 4 rows each ----
    const int l_sg  = tid & 7;               // 16B segment within 128B row
    const int l_rw0 = tid >> 3;              // base row 0..31 (j adds 32)

    // ---- warp / mma coords: 2(M) x 4(N), warp tile 64x32 ----
    const int warp_m = wid & 1;
    const int warp_n = wid >> 1;
    const uint32_t l_row = (uint32_t)((lid & 7) + ((lid >> 3) & 1) * 8);
    const uint32_t l_k   = (uint32_t)(lid >> 4) * 16u;    // byte col offset (0/16)

    // precomputed swizzle bases: rows are 128B-aligned, kb<128, so
    // sw128(base + kb) = base + (kb ^ ((base>>3)&0x70))
    uint32_t a_base[4], a_xor[4];
    #pragma unroll
    for (int mt = 0; mt < 4; mt++) {
        uint32_t base = ((uint32_t)(warp_m * 64 + mt * 16) + l_row) * 128u;
        a_base[mt] = sb + A_OFF + base;
        a_xor[mt]  = (base >> 3) & 0x70u;
    }
    uint32_t b_base[2], b_xor[2];
    #pragma unroll
    for (int nf2 = 0; nf2 < 2; nf2++) {
        uint32_t base = ((uint32_t)(warp_n * 32 + nf2 * 16) + l_row) * 128u;
        b_base[nf2] = sb + B_OFF + base;
        b_xor[nf2]  = (base >> 3) & 0x70u;
    }

    float d[4][4][4];
    #pragma unroll
    for (int mt = 0; mt < 4; mt++)
        #pragma unroll
        for (int nf = 0; nf < 4; nf++)
            #pragma unroll
            for (int r = 0; r < 4; r++) d[mt][nf][r] = 0.f;

    // issue one stage: A raw f32 gather + B copies, one commit group
    auto issue_stage = [&](int c, uint32_t stg) {
        #pragma unroll
        for (int j = 0; j < 4; j++) {
            int row = l_rw0 + j * 32;
            uint32_t o = sw128((uint32_t)row * 128u + (uint32_t)l_sg * 16u);
            const float* asrc = weight + (size_t)sids[row] * D_K + c * KC + l_sg * 4;
            cp16(sb + stg + A_OFF + o, asrc);
            const float* bsrc = g_xt + (size_t)(n0 + row) * D_K + c * KC + l_sg * 4;
            cp16(sb + stg + B_OFF + o, bsrc);
        }
        cp_commit();
    };

    // ---------- prologue: stages 0, 1 ----------
    issue_stage(0, 0);
    issue_stage(1, STAGE);

    // ---------- main loop (2-stage: wait, bar, compute, bar, issue) ----------
    for (int c = 0; c < NCH; c++) {
        cp_wait<1>();                        // chunk c landed (c+1 may be in flight)
        __syncthreads();

        const uint32_t cur = (uint32_t)(c & 1) * STAGE;

        // ---- compute chunk c: 4 k-steps of 8 ----
        #pragma unroll
        for (int ks8 = 0; ks8 < 4; ks8++) {
            const uint32_t kb = (uint32_t)ks8 * 32u + l_k;   // byte col (<128)
            uint32_t a[4][4], b[4][2];
            #pragma unroll
            for (int mt = 0; mt < 4; mt++)
                ldsm4(cur + a_base[mt] + (kb ^ a_xor[mt]),
                      a[mt][0], a[mt][1], a[mt][2], a[mt][3]);
            #pragma unroll
            for (int nf2 = 0; nf2 < 2; nf2++)
                // x4 over 16 n-rows: r0/r2 -> nf even, r1/r3 -> nf odd
                ldsm4(cur + b_base[nf2] + (kb ^ b_xor[nf2]),
                      b[2*nf2][0], b[2*nf2+1][0], b[2*nf2][1], b[2*nf2+1][1]);
            #pragma unroll
            for (int mt = 0; mt < 4; mt++)
                #pragma unroll
                for (int nf = 0; nf < 4; nf++)
                    mma_tf32(d[mt][nf], a[mt], b[nf]);
        }

        __syncthreads();                     // all warps done reading buffer (c&1)

        if (c + 2 < NCH) issue_stage(c + 2, cur);   // refill the freed buffer
        else             cp_commit();        // keep group count in step
    }

    // ---------- epilogue: C[n][m] stride 132 (conflict-free both phases) ----
    float* C = reinterpret_cast<float*>(smc);   // 128 x 132 f32 = 67.6KB
    #pragma unroll
    for (int mt = 0; mt < 4; mt++) {
        int m = warp_m * 64 + mt * 16 + (lid >> 2);
        float b0v = sbias[m];
        float b1v = sbias[m + 8];
        #pragma unroll
        for (int nf = 0; nf < 4; nf++) {
            int n = warp_n * 32 + nf * 8 + (lid & 3) * 2;
            C[(size_t)n * CSTRIDE + m]            = d[mt][nf][0] + b0v;
            C[(size_t)(n + 1) * CSTRIDE + m]      = d[mt][nf][1] + b0v;
            C[(size_t)n * CSTRIDE + m + 8]        = d[mt][nf][2] + b1v;
            C[(size_t)(n + 1) * CSTRIDE + m + 8]  = d[mt][nf][3] + b1v;
        }
    }
    __syncthreads();

    // read phase: warp w owns rows n = w*16..w*16+15; lanes span 128 samples
    {
        #pragma unroll
        for (int j = 0; j < 16; j++) {
            int n = wid * 16 + j;
            float4 v = *reinterpret_cast<const float4*>(&C[(size_t)n * CSTRIDE + lid * 4]);
            *reinterpret_cast<float4*>(out + (size_t)(n0 + n) * S_ALL + s0 + lid * 4) = v;
        }
    }
}

extern "C" void kernel_launch(void* const* d_in, const int* in_sizes, int n_in,
                              void* d_out, int out_size)
{
    const float* x    = (const float*)d_in[0];
    const float* w    = (const float*)d_in[1];
    const float* bias = (const float*)d_in[2];
    const int*   ids  = (const int*)d_in[3];
    float*       out  = (float*)d_out;

    cudaFuncSetAttribute(lsh_mma_gemm, cudaFuncAttributeMaxDynamicSharedMemorySize,
                         SMEM_BYTES);

    round_x_kernel<<<128, 256>>>(x);
    dim3 grid(NX / NTILE, S_ALL / STILE);   // (2, 256): n-half fastest -> L2 reuse
    lsh_mma_gemm<<<grid, THREADS, SMEM_BYTES>>>(w, bias, ids, out);
}